// round 14
// baseline (speedup 1.0000x reference)
#include <cuda_runtime.h>
#include <cuda_bf16.h>
#include <math.h>
#include <stdint.h>

// Problem constants
#define NN 50000
#define EE 400000
#define EP 450000      // E + N self loops
#define FF 128
#define H1 8
#define CC 64
#define HC 512         // H1*CC
#define BB 64
#define KK 10

// ---------------- scratch (device globals; no allocation allowed) ----------------
__device__ float g_h1[(size_t)NN * HC / 2];  // bf16[NN*HC]
__device__ float g_out1[(size_t)NN * HC];    // elu(gat1), fp32 (gemm2 input)
__device__ float g_h2[(size_t)NN * CC / 2];  // bf16[NN*CC]
__device__ float g_as1[NN * H1];
__device__ float g_ad1[NN * H1];
__device__ float g_as2[NN];
__device__ float g_ad2[NN];
__device__ int   g_rowptr[NN + 1];
__device__ int   g_cursor[NN];
__device__ int   g_srcsorted[EP];
__device__ float g_pooled[BB * CC];
__device__ float g_W1T[HC * FF];             // W1^T : [512,128] (K-major B operand)
__device__ float g_W2T[CC * HC];             // W2^T : [64,512]

// ================= mma.sync helpers (sm_80+ PTX; valid on plain sm_103) =========
__device__ __forceinline__ void ldm_x4(uint32_t* r, uint32_t addr) {
    asm volatile("ldmatrix.sync.aligned.m8n8.x4.shared.b16 {%0,%1,%2,%3}, [%4];"
        : "=r"(r[0]), "=r"(r[1]), "=r"(r[2]), "=r"(r[3]) : "r"(addr));
}
__device__ __forceinline__ void ldm_x2(uint32_t* r, uint32_t addr) {
    asm volatile("ldmatrix.sync.aligned.m8n8.x2.shared.b16 {%0,%1}, [%2];"
        : "=r"(r[0]), "=r"(r[1]) : "r"(addr));
}
__device__ __forceinline__ void mma_bf16(float* c, const uint32_t* a, const uint32_t* b) {
    asm volatile("mma.sync.aligned.m16n8k16.row.col.f32.bf16.bf16.f32 "
        "{%0,%1,%2,%3}, {%4,%5,%6,%7}, {%8,%9}, {%0,%1,%2,%3};"
        : "+f"(c[0]), "+f"(c[1]), "+f"(c[2]), "+f"(c[3])
        : "r"(a[0]), "r"(a[1]), "r"(a[2]), "r"(a[3]), "r"(b[0]), "r"(b[1]));
}

// split a float into bf16 hi + bf16 lo (residual)
__device__ __forceinline__ void bsplit(float x, uint32_t& h, uint32_t& l) {
    __nv_bfloat16 hb = __float2bfloat16(x);
    float r = x - __bfloat162float(hb);
    h = (uint32_t)__bfloat16_as_ushort(hb);
    l = (uint32_t)__bfloat16_as_ushort(__float2bfloat16(r));
}
__device__ __forceinline__ void bsplit4(float4 v, uint2& hi, uint2& lo) {
    uint32_t h0, l0, h1, l1, h2, l2, h3, l3;
    bsplit(v.x, h0, l0); bsplit(v.y, h1, l1);
    bsplit(v.z, h2, l2); bsplit(v.w, h3, l3);
    hi.x = h0 | (h1 << 16); hi.y = h2 | (h3 << 16);
    lo.x = l0 | (l1 << 16); lo.y = l2 | (l3 << 16);
}

// ================= bf16x3 tensor-core GEMM + fused attention dots ==============
// C[M,NTOT] = A[M,KTOT] @ BT[NTOT,KTOT]^T   (BT K-major).
// 3 passes: Ahi*Bhi + Alo*Bhi + Ahi*Blo (full bf16x3 — R13 showed the weight-lo
// term is systematic error and CANNOT be dropped).
// C stored as packed bf16x2. Fused epilogue: attention dot products (fp32 accs).
template <int KTOT, int BN>
__global__ void __launch_bounds__(256, 2) gemm_bf16x3_kernel(
    const float* __restrict__ A, const float* __restrict__ BT,
    float* __restrict__ C, int M, int NTOT,
    const float* __restrict__ attS, const float* __restrict__ attD,
    float* __restrict__ as_out, float* __restrict__ ad_out, int hstride) {
    constexpr int BM = 128, BK = 32;
    constexpr int NPANEL = KTOT / BK;
    constexpr int LDB_BYTES = 80;     // 32 bf16 padded to 40 (80 bytes)
    constexpr int WN = BN / 4;        // warp n-tile (32 or 16)
    constexpr int NT = WN / 8;        // n mma tiles per warp (4 or 2)
    constexpr int AV = 4;             // A float4 per thread
    constexpr int BV = (BN * 8) / 256;

    __shared__ __align__(16) char sAhi[BM * LDB_BYTES];
    __shared__ __align__(16) char sAlo[BM * LDB_BYTES];
    __shared__ __align__(16) char sBhi[BN * LDB_BYTES];
    __shared__ __align__(16) char sBlo[BN * LDB_BYTES];

    const int tid = threadIdx.x, wid = tid >> 5, lane = tid & 31;
    const int wm = wid & 1, wn = wid >> 1;   // 2 x 4 warp grid
    const int m0 = blockIdx.y * BM, n0 = blockIdx.x * BN;

    const uint32_t aHiB = (uint32_t)__cvta_generic_to_shared(sAhi);
    const uint32_t aLoB = (uint32_t)__cvta_generic_to_shared(sAlo);
    const uint32_t bHiB = (uint32_t)__cvta_generic_to_shared(sBhi);
    const uint32_t bLoB = (uint32_t)__cvta_generic_to_shared(sBlo);

    float acc[4][NT][4];
#pragma unroll
    for (int i = 0; i < 4; i++)
#pragma unroll
        for (int j = 0; j < NT; j++)
#pragma unroll
            for (int q = 0; q < 4; q++) acc[i][j][q] = 0.f;

    const int a_row = lane & 15;
    const int a_col = (lane >> 4) << 3;
    const int b_row = lane & 7;
    const int b_col = ((lane >> 3) & 1) << 3;

    const int a_frow = tid >> 3;
    const int a_fc4  = tid & 7;

    auto loadA = [&](int k0, float4* av) {
#pragma unroll
        for (int i = 0; i < AV; i++) {
            int row = a_frow + i * 32;
            int gm = m0 + row;
            av[i] = (gm < M)
                ? __ldg(reinterpret_cast<const float4*>(A + (size_t)gm * KTOT + k0 + a_fc4 * 4))
                : make_float4(0.f, 0.f, 0.f, 0.f);
        }
    };

    float4 av[AV];
    loadA(0, av);

    for (int p = 0; p < NPANEL; ++p) {
        int k0 = p * BK;
        float4 bv[BV];
#pragma unroll
        for (int i = 0; i < BV; i++) {
            int row = a_frow + i * 32;
            bv[i] = __ldg(reinterpret_cast<const float4*>(BT + (size_t)(n0 + row) * KTOT + k0 + a_fc4 * 4));
        }
        __syncthreads();   // previous compute done with smem
#pragma unroll
        for (int i = 0; i < AV; i++) {
            int row = a_frow + i * 32;
            uint2 hi, lo;
            bsplit4(av[i], hi, lo);
            int off = row * LDB_BYTES + a_fc4 * 8;
            *reinterpret_cast<uint2*>(sAhi + off) = hi;
            *reinterpret_cast<uint2*>(sAlo + off) = lo;
        }
#pragma unroll
        for (int i = 0; i < BV; i++) {
            int row = a_frow + i * 32;
            uint2 hi, lo;
            bsplit4(bv[i], hi, lo);
            int off = row * LDB_BYTES + a_fc4 * 8;
            *reinterpret_cast<uint2*>(sBhi + off) = hi;
            *reinterpret_cast<uint2*>(sBlo + off) = lo;
        }
        __syncthreads();
        if (p + 1 < NPANEL) loadA(k0 + BK, av);   // prefetch next A panel
#pragma unroll
        for (int ks = 0; ks < 2; ks++) {
            int kk = ks * 16;
            uint32_t ah[4][4], al[4][4], bh[NT][2], bl[NT][2];
#pragma unroll
            for (int mt = 0; mt < 4; mt++) {
                uint32_t off = (uint32_t)((wm * 64 + mt * 16 + a_row) * LDB_BYTES + (kk + a_col) * 2);
                ldm_x4(ah[mt], aHiB + off);
                ldm_x4(al[mt], aLoB + off);
            }
#pragma unroll
            for (int nt = 0; nt < NT; nt++) {
                uint32_t off = (uint32_t)((wn * WN + nt * 8 + b_row) * LDB_BYTES + (kk + b_col) * 2);
                ldm_x2(bh[nt], bHiB + off);
                ldm_x2(bl[nt], bLoB + off);
            }
#pragma unroll
            for (int mt = 0; mt < 4; mt++)
#pragma unroll
                for (int nt = 0; nt < NT; nt++) mma_bf16(acc[mt][nt], ah[mt], bh[nt]);
#pragma unroll
            for (int mt = 0; mt < 4; mt++)
#pragma unroll
                for (int nt = 0; nt < NT; nt++) mma_bf16(acc[mt][nt], al[mt], bh[nt]);
#pragma unroll
            for (int mt = 0; mt < 4; mt++)
#pragma unroll
                for (int nt = 0; nt < NT; nt++) mma_bf16(acc[mt][nt], ah[mt], bl[nt]);
        }
    }

    // ---- epilogue: store C (packed bf16x2) + fused attention dots ----
    const int h = (n0 + wn * WN) >> 6;
#pragma unroll
    for (int mt = 0; mt < 4; mt++) {
        int r0 = m0 + wm * 64 + mt * 16 + (lane >> 2);
        int r1 = r0 + 8;
        float pas0 = 0.f, pad0 = 0.f, pas1 = 0.f, pad1 = 0.f;
#pragma unroll
        for (int nt = 0; nt < NT; nt++) {
            int col = n0 + wn * WN + nt * 8 + (lane & 3) * 2;
            __nv_bfloat16* Cb = reinterpret_cast<__nv_bfloat16*>(C);
            if (r0 < M)
                *reinterpret_cast<__nv_bfloat162*>(Cb + (size_t)r0 * NTOT + col) =
                    __floats2bfloat162_rn(acc[mt][nt][0], acc[mt][nt][1]);
            if (r1 < M)
                *reinterpret_cast<__nv_bfloat162*>(Cb + (size_t)r1 * NTOT + col) =
                    __floats2bfloat162_rn(acc[mt][nt][2], acc[mt][nt][3]);
            float s0 = __ldg(attS + col), s1 = __ldg(attS + col + 1);
            float d0 = __ldg(attD + col), d1 = __ldg(attD + col + 1);
            pas0 += acc[mt][nt][0] * s0 + acc[mt][nt][1] * s1;
            pad0 += acc[mt][nt][0] * d0 + acc[mt][nt][1] * d1;
            pas1 += acc[mt][nt][2] * s0 + acc[mt][nt][3] * s1;
            pad1 += acc[mt][nt][2] * d0 + acc[mt][nt][3] * d1;
        }
#pragma unroll
        for (int o = 1; o <= 2; o <<= 1) {
            pas0 += __shfl_xor_sync(~0u, pas0, o);
            pad0 += __shfl_xor_sync(~0u, pad0, o);
            pas1 += __shfl_xor_sync(~0u, pas1, o);
            pad1 += __shfl_xor_sync(~0u, pad1, o);
        }
        if ((lane & 3) == 0) {
            if (r0 < M) {
                atomicAdd(as_out + (size_t)r0 * hstride + h, pas0);
                atomicAdd(ad_out + (size_t)r0 * hstride + h, pad0);
            }
            if (r1 < M) {
                atomicAdd(as_out + (size_t)r1 * hstride + h, pas1);
                atomicAdd(ad_out + (size_t)r1 * hstride + h, pad1);
            }
        }
    }
}

// ---------------- prep: both weight transposes + zero scratch, one kernel -------
__global__ void prep_kernel(const float* __restrict__ W1, const float* __restrict__ W2) {
    int i = blockIdx.x * blockDim.x + threadIdx.x;
    if (i < FF * HC) {
        int r = i / HC, c = i % HC;
        g_W1T[c * FF + r] = W1[i];
    }
    int j = i - FF * HC;
    if (j >= 0 && j < HC * CC) {
        int r = j / CC, c = j % CC;
        g_W2T[c * HC + r] = W2[j];
    }
    int k = i - FF * HC - HC * CC;
    if (k >= 0 && k < NN) {
        g_cursor[k] = 0;
        g_as2[k] = 0.f;
        g_ad2[k] = 0.f;
        float4 z = make_float4(0.f, 0.f, 0.f, 0.f);
        float4* p1 = reinterpret_cast<float4*>(g_as1 + k * H1);
        p1[0] = z; p1[1] = z;
        float4* p2 = reinterpret_cast<float4*>(g_ad1 + k * H1);
        p2[0] = z; p2[1] = z;
    }
    if (k >= 0 && k < BB * CC) g_pooled[k] = 0.f;
}

// ---------------- CSR build ----------------
__global__ void count_edges_kernel(const int* __restrict__ ei) {
    int i = blockIdx.x * blockDim.x + threadIdx.x;
    if (i >= EP) return;
    int d = (i < EE) ? ei[EE + i] : (i - EE);
    atomicAdd(&g_cursor[d], 1);
}

__global__ void scan_kernel() {
    __shared__ int part[1024];
    int t = threadIdx.x;
    const int CH = (NN + 1023) / 1024;  // 49
    int base = t * CH;
    int s = 0;
    for (int i = 0; i < CH; i++) {
        int idx = base + i;
        if (idx < NN) s += g_cursor[idx];
    }
    part[t] = s;
    __syncthreads();
    for (int o = 1; o < 1024; o <<= 1) {
        int v = (t >= o) ? part[t - o] : 0;
        __syncthreads();
        part[t] += v;
        __syncthreads();
    }
    int run = part[t] - s;  // exclusive
    for (int i = 0; i < CH; i++) {
        int idx = base + i;
        if (idx < NN) {
            int c = g_cursor[idx];
            g_rowptr[idx] = run;
            g_cursor[idx] = run;
            run += c;
        }
    }
    if (t == 1023) g_rowptr[NN] = part[1023];
}

__global__ void scatter_edges_kernel(const int* __restrict__ ei) {
    int i = blockIdx.x * blockDim.x + threadIdx.x;
    if (i >= EP) return;
    int s, d;
    if (i < EE) { s = ei[i]; d = ei[EE + i]; }
    else        { s = i - EE; d = s; }
    int pos = atomicAdd(&g_cursor[d], 1);
    g_srcsorted[pos] = s;
}

// ---------------- layer-1 aggregation (softmax + weighted sum + elu) ----------------
// block = node, warp = head. BF16 gathers, 4-way MLP unroll.
__global__ void agg1_kernel(const float* __restrict__ bias) {
    __shared__ float ebuf[H1][64];
    int n = blockIdx.x;
    int h = threadIdx.x >> 5;
    int lane = threadIdx.x & 31;
    int base = g_rowptr[n];
    int deg = g_rowptr[n + 1] - base;
    float adn = g_ad1[n * H1 + h];

    float m = -INFINITY;
    for (int j = lane; j < deg; j += 32) {
        int s = g_srcsorted[base + j];
        float e = g_as1[s * H1 + h] + adn;
        e = e > 0.f ? e : 0.2f * e;
        if (j < 64) ebuf[h][j] = e;
        m = fmaxf(m, e);
    }
#pragma unroll
    for (int o = 16; o; o >>= 1) m = fmaxf(m, __shfl_xor_sync(~0u, m, o));

    float sum = 0.f;
    for (int j = lane; j < deg; j += 32) {
        float e;
        if (j < 64) e = ebuf[h][j];
        else {
            int s = g_srcsorted[base + j];
            e = g_as1[s * H1 + h] + adn;
            e = e > 0.f ? e : 0.2f * e;
        }
        sum += __expf(e - m);
    }
#pragma unroll
    for (int o = 16; o; o >>= 1) sum += __shfl_xor_sync(~0u, sum, o);
    float inv = 1.f / (sum + 1e-16f);
    __syncwarp();

    const __nv_bfloat162* H = reinterpret_cast<const __nv_bfloat162*>(g_h1);
    const int off = h * 32 + lane;
    float acc0 = 0.f, acc1 = 0.f;
    auto edgeE = [&](int j) -> float {
        if (j < 64) return ebuf[h][j];
        int s = g_srcsorted[base + j];
        float e = g_as1[s * H1 + h] + adn;
        return e > 0.f ? e : 0.2f * e;
    };
    int j = 0;
    for (; j + 4 <= deg; j += 4) {
        int s0 = g_srcsorted[base + j];
        int s1 = g_srcsorted[base + j + 1];
        int s2 = g_srcsorted[base + j + 2];
        int s3 = g_srcsorted[base + j + 3];
        float a0 = __expf(edgeE(j) - m) * inv;
        float a1 = __expf(edgeE(j + 1) - m) * inv;
        float a2 = __expf(edgeE(j + 2) - m) * inv;
        float a3 = __expf(edgeE(j + 3) - m) * inv;
        float2 v0 = __bfloat1622float2(H[(size_t)s0 * 256 + off]);
        float2 v1 = __bfloat1622float2(H[(size_t)s1 * 256 + off]);
        float2 v2 = __bfloat1622float2(H[(size_t)s2 * 256 + off]);
        float2 v3 = __bfloat1622float2(H[(size_t)s3 * 256 + off]);
        acc0 += v0.x * a0 + v1.x * a1 + v2.x * a2 + v3.x * a3;
        acc1 += v0.y * a0 + v1.y * a1 + v2.y * a2 + v3.y * a3;
    }
    for (; j < deg; j++) {
        int s0 = g_srcsorted[base + j];
        float a0 = __expf(edgeE(j) - m) * inv;
        float2 v0 = __bfloat1622float2(H[(size_t)s0 * 256 + off]);
        acc0 += v0.x * a0;
        acc1 += v0.y * a0;
    }
    int c0 = h * CC + 2 * lane;
    float v0 = acc0 + bias[c0];
    float v1 = acc1 + bias[c0 + 1];
    v0 = v0 > 0.f ? v0 : expm1f(v0);
    v1 = v1 > 0.f ? v1 : expm1f(v1);
    *reinterpret_cast<float2*>(g_out1 + (size_t)n * HC + c0) = make_float2(v0, v1);
}

// ---------------- layer-2 aggregation + fused global_add_pool ----------------
// warp = node (8 per block; 6250*8 = 50000 exactly). Pool via per-block smem
// reduction: batch-uniform blocks (~99%, batch sorted) do one 64-wide atomicAdd.
__global__ void agg2_pool_kernel(const float* __restrict__ bias, const int* __restrict__ batch) {
    __shared__ float ebuf[8][64];
    __shared__ float sacc[8][64];
    __shared__ int sbt[8];
    int w = threadIdx.x >> 5;
    int lane = threadIdx.x & 31;
    int n = blockIdx.x * 8 + w;
    int base = g_rowptr[n];
    int deg = g_rowptr[n + 1] - base;
    float adn = g_ad2[n];

    float m = -INFINITY;
    for (int j = lane; j < deg; j += 32) {
        int s = g_srcsorted[base + j];
        float e = g_as2[s] + adn;
        e = e > 0.f ? e : 0.2f * e;
        if (j < 64) ebuf[w][j] = e;
        m = fmaxf(m, e);
    }
#pragma unroll
    for (int o = 16; o; o >>= 1) m = fmaxf(m, __shfl_xor_sync(~0u, m, o));

    float sum = 0.f;
    for (int j = lane; j < deg; j += 32) {
        float e;
        if (j < 64) e = ebuf[w][j];
        else {
            int s = g_srcsorted[base + j];
            e = g_as2[s] + adn;
            e = e > 0.f ? e : 0.2f * e;
        }
        sum += __expf(e - m);
    }
#pragma unroll
    for (int o = 16; o; o >>= 1) sum += __shfl_xor_sync(~0u, sum, o);
    float inv = 1.f / (sum + 1e-16f);
    __syncwarp();

    const __nv_bfloat162* H = reinterpret_cast<const __nv_bfloat162*>(g_h2);
    float acc0 = 0.f, acc1 = 0.f;
    auto edgeE = [&](int j) -> float {
        if (j < 64) return ebuf[w][j];
        int s = g_srcsorted[base + j];
        float e = g_as2[s] + adn;
        return e > 0.f ? e : 0.2f * e;
    };
    int j = 0;
    for (; j + 4 <= deg; j += 4) {
        int s0 = g_srcsorted[base + j];
        int s1 = g_srcsorted[base + j + 1];
        int s2 = g_srcsorted[base + j + 2];
        int s3 = g_srcsorted[base + j + 3];
        float a0 = __expf(edgeE(j) - m) * inv;
        float a1 = __expf(edgeE(j + 1) - m) * inv;
        float a2 = __expf(edgeE(j + 2) - m) * inv;
        float a3 = __expf(edgeE(j + 3) - m) * inv;
        float2 v0 = __bfloat1622float2(H[(size_t)s0 * 32 + lane]);
        float2 v1 = __bfloat1622float2(H[(size_t)s1 * 32 + lane]);
        float2 v2 = __bfloat1622float2(H[(size_t)s2 * 32 + lane]);
        float2 v3 = __bfloat1622float2(H[(size_t)s3 * 32 + lane]);
        acc0 += v0.x * a0 + v1.x * a1 + v2.x * a2 + v3.x * a3;
        acc1 += v0.y * a0 + v1.y * a1 + v2.y * a2 + v3.y * a3;
    }
    for (; j < deg; j++) {
        int s0 = g_srcsorted[base + j];
        float a0 = __expf(edgeE(j) - m) * inv;
        float2 v0 = __bfloat1622float2(H[(size_t)s0 * 32 + lane]);
        acc0 += v0.x * a0;
        acc1 += v0.y * a0;
    }
    int c0 = 2 * lane;
    float v0 = acc0 + bias[c0];
    float v1 = acc1 + bias[c0 + 1];
    v0 = v0 > 0.f ? v0 : expm1f(v0);
    v1 = v1 > 0.f ? v1 : expm1f(v1);

    sacc[w][c0] = v0;
    sacc[w][c0 + 1] = v1;
    if (lane == 0) sbt[w] = batch[n];
    __syncthreads();

    int t = threadIdx.x;
    if (t < CC) {
        int bt0 = sbt[0];
        bool uni = true;
#pragma unroll
        for (int q = 1; q < 8; q++) uni &= (sbt[q] == bt0);
        if (uni) {
            float s = 0.f;
#pragma unroll
            for (int q = 0; q < 8; q++) s += sacc[q][t];
            atomicAdd(&g_pooled[bt0 * CC + t], s);
        } else {
#pragma unroll
            for (int q = 0; q < 8; q++)
                atomicAdd(&g_pooled[sbt[q] * CC + t], sacc[q][t]);
        }
    }
}

// ---------------- MLP head + log_softmax ----------------
__global__ void head_kernel(const float* __restrict__ lin1_w, const float* __restrict__ lin1_b,
                            const float* __restrict__ lin2_w, const float* __restrict__ lin2_b,
                            float* __restrict__ out) {
    __shared__ float p[CC], z[CC], lg[KK];
    __shared__ float lse;
    int t = threadIdx.x;
    int g = blockIdx.x;
    p[t] = g_pooled[g * CC + t];
    __syncthreads();
    float zz = lin1_b[t];
    for (int i = 0; i < CC; i++) zz += p[i] * lin1_w[i * CC + t];
    zz = zz > 0.f ? zz : expm1f(zz);
    z[t] = zz;
    __syncthreads();
    if (t < KK) {
        float l = lin2_b[t];
        for (int i = 0; i < CC; i++) l += z[i] * lin2_w[i * KK + t];
        lg[t] = l;
    }
    __syncthreads();
    if (t == 0) {
        float m = -INFINITY;
        for (int i = 0; i < KK; i++) m = fmaxf(m, lg[i]);
        float s = 0.f;
        for (int i = 0; i < KK; i++) s += expf(lg[i] - m);
        lse = m + logf(s);
    }
    __syncthreads();
    if (t < KK) out[g * KK + t] = lg[t] - lse;
}

// ---------------- launch ----------------
extern "C" void kernel_launch(void* const* d_in, const int* in_sizes, int n_in,
                              void* d_out, int out_size) {
    const float* x        = (const float*)d_in[0];
    const int*   ei       = (const int*)d_in[1];
    const int*   batch    = (const int*)d_in[2];
    const float* W1       = (const float*)d_in[3];
    const float* att_src1 = (const float*)d_in[4];
    const float* att_dst1 = (const float*)d_in[5];
    const float* b1       = (const float*)d_in[6];
    const float* W2       = (const float*)d_in[7];
    const float* att_src2 = (const float*)d_in[8];
    const float* att_dst2 = (const float*)d_in[9];
    const float* b2       = (const float*)d_in[10];
    const float* lin1_w   = (const float*)d_in[11];
    const float* lin1_b   = (const float*)d_in[12];
    const float* lin2_w   = (const float*)d_in[13];
    const float* lin2_b   = (const float*)d_in[14];
    float* out = (float*)d_out;

    float *w1t, *w2t, *h1, *o1, *h2, *as1, *ad1, *as2, *ad2;
    cudaGetSymbolAddress((void**)&w1t, g_W1T);
    cudaGetSymbolAddress((void**)&w2t, g_W2T);
    cudaGetSymbolAddress((void**)&h1, g_h1);
    cudaGetSymbolAddress((void**)&o1, g_out1);
    cudaGetSymbolAddress((void**)&h2, g_h2);
    cudaGetSymbolAddress((void**)&as1, g_as1);
    cudaGetSymbolAddress((void**)&ad1, g_ad1);
    cudaGetSymbolAddress((void**)&as2, g_as2);
    cudaGetSymbolAddress((void**)&ad2, g_ad2);

    // prep: weight transposes + zero scratch (one kernel)
    const int PREP_TOTAL = FF * HC + HC * CC + NN;
    prep_kernel<<<(PREP_TOTAL + 255) / 256, 256>>>(W1, W2);

    // CSR build
    count_edges_kernel<<<(EP + 255) / 256, 256>>>(ei);
    scan_kernel<<<1, 1024>>>();
    scatter_edges_kernel<<<(EP + 255) / 256, 256>>>(ei);

    // layer 1: h1 = x @ W1 (bf16x3 tensor cores, bf16 output) + fused att1 dots
    {
        dim3 grid(HC / 128, (NN + 127) / 128);
        gemm_bf16x3_kernel<FF, 128><<<grid, 256>>>(x, w1t, h1, NN, HC,
                                                   att_src1, att_dst1, as1, ad1, H1);
    }
    agg1_kernel<<<NN, 256>>>(b1);

    // layer 2: h2 = out1 @ W2 (bf16 output) + fused att2 dots
    {
        dim3 grid(CC / 64, (NN + 127) / 128);
        gemm_bf16x3_kernel<HC, 64><<<grid, 256>>>(o1, w2t, h2, NN, CC,
                                                  att_src2, att_dst2, as2, ad2, 1);
    }
    // layer-2 aggregation with fused pooling
    agg2_pool_kernel<<<NN / 8, 256>>>(b2, batch);

    // head
    head_kernel<<<BB, CC>>>(lin1_w, lin1_b, lin2_w, lin2_b, out);
}